// round 2
// baseline (speedup 1.0000x reference)
#include <cuda_runtime.h>

// PointPairNet: B=4, N=512, D=3. Layers: pair-relu(64) -> 64 -> 128, global max-pool, head MLP.
// Strategy: precompute Ai/Aj (layer-1 split), fused pairwise MLP with packed fp32x2 FMA,
// max-pool via monotone-key atomicMax, tiny head kernel.

#define BATCH 4
#define NPTS  512
#define C1    64
#define C3    128

// ---------------- device scratch (no allocations allowed) ----------------
__device__ float    g_Ai[BATCH * NPTS * C1];   // Ai + b1 folded
__device__ float    g_Aj[BATCH * NPTS * C1];
__device__ unsigned g_Pkey[BATCH * C3];        // monotone float keys for max

// ---------------- f32x2 helpers ----------------
static __device__ __forceinline__ unsigned long long splat2(float x) {
    unsigned long long d; unsigned xi = __float_as_uint(x);
    asm("mov.b64 %0, {%1, %1};" : "=l"(d) : "r"(xi));
    return d;
}
static __device__ __forceinline__ unsigned long long ffma2(unsigned long long a,
                                                           unsigned long long b,
                                                           unsigned long long c) {
    unsigned long long d;
    asm("fma.rn.f32x2 %0, %1, %2, %3;" : "=l"(d) : "l"(a), "l"(b), "l"(c));
    return d;
}
static __device__ __forceinline__ void unpack2(unsigned long long v, float& lo, float& hi) {
    unsigned a, b;
    asm("mov.b64 {%0, %1}, %2;" : "=r"(a), "=r"(b) : "l"(v));
    lo = __uint_as_float(a); hi = __uint_as_float(b);
}
static __device__ __forceinline__ unsigned long long pack2(float lo, float hi) {
    unsigned long long d;
    asm("mov.b64 %0, {%1, %2};" : "=l"(d) : "r"(__float_as_uint(lo)), "r"(__float_as_uint(hi)));
    return d;
}
static __device__ __forceinline__ unsigned long long max2(unsigned long long a, unsigned long long b) {
    float al, ah, bl, bh; unpack2(a, al, ah); unpack2(b, bl, bh);
    return pack2(fmaxf(al, bl), fmaxf(ah, bh));
}
// monotone float->uint key (order preserving), inverse for decode
static __device__ __forceinline__ unsigned fkey(float f) {
    unsigned u = __float_as_uint(f);
    return (u >> 31) ? ~u : (u | 0x80000000u);
}
static __device__ __forceinline__ float funkey(unsigned k) {
    return __uint_as_float((k >> 31) ? (k & 0x7fffffffu) : ~k);
}

// ---------------- kernels ----------------
__global__ void k_init() {
    int t = blockIdx.x * blockDim.x + threadIdx.x;
    if (t < BATCH * C3) g_Pkey[t] = 0u;  // below key of any finite float
}

__global__ void k_pre(const float* __restrict__ X, const float* __restrict__ W1,
                      const float* __restrict__ b1) {
    int ng = blockIdx.x;        // b*512 + n, 0..2047
    int c  = threadIdx.x;       // 0..63
    float x0 = X[ng * 3 + 0], x1 = X[ng * 3 + 1], x2 = X[ng * 3 + 2];
    const float* w = W1 + c * 6;
    g_Aj[ng * 64 + c] = x0 * w[0] + x1 * w[1] + x2 * w[2];
    g_Ai[ng * 64 + c] = b1[c] + x0 * w[3] + x1 * w[4] + x2 * w[5];
}

// SMEM layout (float offsets). Rows padded to kill bank conflicts; even strides keep 8B alignment.
#define W2T_OFF 0        // [k][c]  stride 66 -> 64*66 = 4224
#define W3T_OFF 4224     // [k][c3] stride 130 -> 64*130 = 8320
#define AJT_OFF 12544    // [k][jj] stride 65 -> 64*65 = 4160
#define AIT_OFF 16704    // [k][ii] stride 8  -> 512
#define B2_OFF  17216    // 64
#define H2_OFF  17280    // [pair][k] stride 65 -> 512*65 = 33280
#define MAX_OFF 50560    // 128 unsigned
#define SMEM_FLOATS 50688
#define SMEM_BYTES (SMEM_FLOATS * 4)

// CTA: b fixed, 8 i-rows x 64 j-cols = 512 pairs, 256 threads, 2 pairs/thread (i and i+4).
__global__ void __launch_bounds__(256, 1)
k_main(const float* __restrict__ W2, const float* __restrict__ b2,
       const float* __restrict__ W3) {
    extern __shared__ float sm[];
    unsigned long long* smu = reinterpret_cast<unsigned long long*>(sm);
    unsigned* sMax = reinterpret_cast<unsigned*>(sm + MAX_OFF);

    const int tid = threadIdx.x;
    const int jt = blockIdx.x;   // 0..7
    const int it = blockIdx.y;   // 0..63
    const int b  = blockIdx.z;   // 0..3

    // ---- stage weights/activations to SMEM (transposed, padded) ----
    for (int idx = tid; idx < 4096; idx += 256) {         // W2[c][k] -> sW2t[k][c]
        int c = idx >> 6, k = idx & 63;
        sm[W2T_OFF + k * 66 + c] = W2[idx];
    }
    for (int idx = tid; idx < 8192; idx += 256) {         // W3[c3][k] -> sW3t[k][c3]
        int c = idx >> 6, k = idx & 63;
        sm[W3T_OFF + k * 130 + c] = W3[idx];
    }
    {
        const float* gAj = g_Aj + (b * NPTS + jt * 64) * 64;
        for (int idx = tid; idx < 4096; idx += 256) {     // -> sAjT[c][jl]
            int jl = idx >> 6, c = idx & 63;
            sm[AJT_OFF + c * 65 + jl] = gAj[idx];
        }
        const float* gAi = g_Ai + (b * NPTS + it * 8) * 64;
        for (int idx = tid; idx < 512; idx += 256) {      // -> sAiT[c][il]
            int il = idx >> 6, c = idx & 63;
            sm[AIT_OFF + c * 8 + il] = gAi[idx];
        }
    }
    if (tid < 64)  sm[B2_OFF + tid] = b2[tid];
    if (tid < 128) sMax[tid] = 0u;
    __syncthreads();

    const int ii0 = tid >> 6;          // 0..3
    const int jj  = tid & 63;
    const int p0  = ii0 * 64 + jj;     // pair indices within CTA
    const int p1  = (ii0 + 4) * 64 + jj;

    // ---- layer 2: h2 = relu(W2 * relu(Ai+Aj) + b2), 2 pairs per thread ----
    unsigned long long acc0[32], acc1[32];
#pragma unroll
    for (int c2 = 0; c2 < 32; c2++) {
        unsigned long long bb = smu[B2_OFF / 2 + c2];
        acc0[c2] = bb; acc1[c2] = bb;
    }
#pragma unroll 2
    for (int k = 0; k < 64; k++) {
        float aj = sm[AJT_OFF + k * 65 + jj];
        float h0 = fmaxf(sm[AIT_OFF + k * 8 + ii0]     + aj, 0.f);
        float h1 = fmaxf(sm[AIT_OFF + k * 8 + ii0 + 4] + aj, 0.f);
        unsigned long long d0 = splat2(h0), d1 = splat2(h1);
#pragma unroll
        for (int c2 = 0; c2 < 32; c2++) {
            unsigned long long w = smu[W2T_OFF / 2 + k * 33 + c2];  // broadcast LDS.64
            acc0[c2] = ffma2(d0, w, acc0[c2]);
            acc1[c2] = ffma2(d1, w, acc1[c2]);
        }
    }
    // relu + park h2 in padded SMEM (self-read only; no sync needed)
#pragma unroll
    for (int c2 = 0; c2 < 32; c2++) {
        float lo, hi;
        unpack2(acc0[c2], lo, hi);
        sm[H2_OFF + p0 * 65 + 2 * c2]     = fmaxf(lo, 0.f);
        sm[H2_OFF + p0 * 65 + 2 * c2 + 1] = fmaxf(hi, 0.f);
        unpack2(acc1[c2], lo, hi);
        sm[H2_OFF + p1 * 65 + 2 * c2]     = fmaxf(lo, 0.f);
        sm[H2_OFF + p1 * 65 + 2 * c2 + 1] = fmaxf(hi, 0.f);
    }

    // ---- layer 3 (b3 deferred past the max) + pairwise/warp max reduction ----
#pragma unroll 1
    for (int chunk = 0; chunk < 4; chunk++) {
        unsigned long long a3_0[16], a3_1[16];
#pragma unroll
        for (int c2 = 0; c2 < 16; c2++) { a3_0[c2] = 0ULL; a3_1[c2] = 0ULL; }
#pragma unroll 2
        for (int k = 0; k < 64; k++) {
            unsigned long long d0 = splat2(sm[H2_OFF + p0 * 65 + k]);
            unsigned long long d1 = splat2(sm[H2_OFF + p1 * 65 + k]);
#pragma unroll
            for (int c2 = 0; c2 < 16; c2++) {
                unsigned long long w = smu[W3T_OFF / 2 + k * 65 + chunk * 16 + c2];
                a3_0[c2] = ffma2(d0, w, a3_0[c2]);
                a3_1[c2] = ffma2(d1, w, a3_1[c2]);
            }
        }
        unsigned long long m[16];
#pragma unroll
        for (int c2 = 0; c2 < 16; c2++) m[c2] = max2(a3_0[c2], a3_1[c2]);
#pragma unroll
        for (int off = 16; off > 0; off >>= 1) {
#pragma unroll
            for (int c2 = 0; c2 < 16; c2++) {
                unsigned long long o = __shfl_xor_sync(0xffffffffu, m[c2], off);
                m[c2] = max2(m[c2], o);
            }
        }
        if ((tid & 31) == 0) {
#pragma unroll
            for (int c2 = 0; c2 < 16; c2++) {
                float lo, hi; unpack2(m[c2], lo, hi);
                atomicMax(&sMax[chunk * 32 + 2 * c2],     fkey(lo));
                atomicMax(&sMax[chunk * 32 + 2 * c2 + 1], fkey(hi));
            }
        }
    }
    __syncthreads();
    if (tid < 128) atomicMax(&g_Pkey[b * C3 + tid], sMax[tid]);
}

__global__ void k_final(const float* __restrict__ b3, const float* __restrict__ F1,
                        const float* __restrict__ bf1, const float* __restrict__ F2,
                        const float* __restrict__ bf2, float* __restrict__ out) {
    __shared__ float sp[128];
    __shared__ float st[64];
    int t = threadIdx.x;
    for (int b = 0; b < BATCH; b++) {
        if (t < 128) sp[t] = funkey(g_Pkey[b * 128 + t]) + b3[t];
        __syncthreads();
        if (t < 64) {
            float a = bf1[t];
#pragma unroll 4
            for (int c = 0; c < 128; c++) a += F1[t * 128 + c] * sp[c];
            st[t] = fmaxf(a, 0.f);
        }
        __syncthreads();
        if (t < 2) {
            float a = bf2[t];
#pragma unroll
            for (int j = 0; j < 64; j++) a += F2[t * 64 + j] * st[j];
            out[b * 2 + t] = a;
        }
        __syncthreads();
    }
}

// ---------------- launch ----------------
extern "C" void kernel_launch(void* const* d_in, const int* in_sizes, int n_in,
                              void* d_out, int out_size) {
    const float* X   = (const float*)d_in[0];
    const float* W1  = (const float*)d_in[1];
    const float* b1  = (const float*)d_in[2];
    const float* W2  = (const float*)d_in[3];
    const float* b2  = (const float*)d_in[4];
    const float* W3  = (const float*)d_in[5];
    const float* b3  = (const float*)d_in[6];
    const float* F1  = (const float*)d_in[7];
    const float* bf1 = (const float*)d_in[8];
    const float* F2  = (const float*)d_in[9];
    const float* bf2 = (const float*)d_in[10];
    float* out = (float*)d_out;

    cudaFuncSetAttribute(k_main, cudaFuncAttributeMaxDynamicSharedMemorySize, SMEM_BYTES);

    k_init<<<1, 512>>>();
    k_pre<<<BATCH * NPTS, 64>>>(X, W1, b1);
    k_main<<<dim3(8, 64, BATCH), 256, SMEM_BYTES>>>(W2, b2, W3);
    k_final<<<1, 128>>>(b3, F1, bf1, F2, bf2, out);
}

// round 3
// speedup vs baseline: 1.2233x; 1.2233x over previous
#include <cuda_runtime.h>

// PointPairNet: B=4, N=512, D=3. pair-relu(64) -> 64 -> 128, global max-pool, head MLP.
// R2: LDS.128 weight/activation loads; layer3 threads own 8 pairs x 32 ch; FMA-pipe bound.

#define BATCH 4
#define NPTS  512
#define C1    64
#define C3    128

__device__ float    g_Ai[BATCH * NPTS * C1];   // Ai + b1 folded
__device__ float    g_Aj[BATCH * NPTS * C1];
__device__ unsigned g_Pkey[BATCH * C3];        // monotone float keys for max

// ---------------- f32x2 helpers ----------------
static __device__ __forceinline__ unsigned long long splat2(float x) {
    unsigned long long d; unsigned xi = __float_as_uint(x);
    asm("mov.b64 %0, {%1, %1};" : "=l"(d) : "r"(xi));
    return d;
}
static __device__ __forceinline__ unsigned long long ffma2(unsigned long long a,
                                                           unsigned long long b,
                                                           unsigned long long c) {
    unsigned long long d;
    asm("fma.rn.f32x2 %0, %1, %2, %3;" : "=l"(d) : "l"(a), "l"(b), "l"(c));
    return d;
}
static __device__ __forceinline__ void unpack2(unsigned long long v, float& lo, float& hi) {
    unsigned a, b;
    asm("mov.b64 {%0, %1}, %2;" : "=r"(a), "=r"(b) : "l"(v));
    lo = __uint_as_float(a); hi = __uint_as_float(b);
}
static __device__ __forceinline__ unsigned long long pack2(float lo, float hi) {
    unsigned long long d;
    asm("mov.b64 %0, {%1, %2};" : "=l"(d) : "r"(__float_as_uint(lo)), "r"(__float_as_uint(hi)));
    return d;
}
static __device__ __forceinline__ unsigned long long max2(unsigned long long a, unsigned long long b) {
    float al, ah, bl, bh; unpack2(a, al, ah); unpack2(b, bl, bh);
    return pack2(fmaxf(al, bl), fmaxf(ah, bh));
}
static __device__ __forceinline__ unsigned fkey(float f) {
    unsigned u = __float_as_uint(f);
    return (u >> 31) ? ~u : (u | 0x80000000u);
}
static __device__ __forceinline__ float funkey(unsigned k) {
    return __uint_as_float((k >> 31) ? (k & 0x7fffffffu) : ~k);
}

// ---------------- k_pre: layer-1 split + Pkey init folded in ----------------
__global__ void k_pre(const float* __restrict__ X, const float* __restrict__ W1,
                      const float* __restrict__ b1) {
    int ng = blockIdx.x;        // b*512 + n
    int c  = threadIdx.x;       // 0..63
    if (ng < 8) g_Pkey[ng * 64 + c] = 0u;   // key 0 < key of any finite float
    float x0 = X[ng * 3 + 0], x1 = X[ng * 3 + 1], x2 = X[ng * 3 + 2];
    const float* w = W1 + c * 6;
    g_Aj[ng * 64 + c] = x0 * w[0] + x1 * w[1] + x2 * w[2];
    g_Ai[ng * 64 + c] = b1[c] + x0 * w[3] + x1 * w[4] + x2 * w[5];
}

// SMEM layout (float offsets). All rows 16B-aligned for LDS.128.
#define W2T_OFF 0        // [k][c]  stride 68  -> 64*68  = 4352
#define W3T_OFF 4352     // [k][c3] stride 132 -> 64*132 = 8448
#define AJT_OFF 12800    // [k][jj] stride 65  -> 64*65  = 4160
#define AIT_OFF 16960    // [k][ii] stride 8   -> 512
#define B2_OFF  17472    // 64
#define H2_OFF  17536    // [pair][ch] stride 68 -> 512*68 = 34816
#define MAX_OFF 52352    // 128 unsigned
#define SMEM_FLOATS 52480
#define SMEM_BYTES (SMEM_FLOATS * 4)

// CTA: b fixed, 8 i-rows x 64 j-cols = 512 pairs, 256 threads.
__global__ void __launch_bounds__(256, 1)
k_main(const float* __restrict__ W2, const float* __restrict__ b2,
       const float* __restrict__ W3) {
    extern __shared__ float sm[];
    unsigned long long* smu = reinterpret_cast<unsigned long long*>(sm);
    unsigned* sMax = reinterpret_cast<unsigned*>(sm + MAX_OFF);

    const int tid = threadIdx.x;
    const int jt = blockIdx.x;   // 0..7
    const int it = blockIdx.y;   // 0..63
    const int b  = blockIdx.z;   // 0..3

    // ---- stage weights/activations (transposed, padded, 16B-aligned rows) ----
    for (int idx = tid; idx < 4096; idx += 256) {         // W2[c][k] -> sW2t[k][c]
        int c = idx >> 6, k = idx & 63;
        sm[W2T_OFF + k * 68 + c] = W2[idx];
    }
    for (int idx = tid; idx < 8192; idx += 256) {         // W3[c3][k] -> sW3t[k][c3]
        int c = idx >> 6, k = idx & 63;
        sm[W3T_OFF + k * 132 + c] = W3[idx];
    }
    {
        const float* gAj = g_Aj + (b * NPTS + jt * 64) * 64;
        for (int idx = tid; idx < 4096; idx += 256) {     // -> sAjT[k][jl]
            int jl = idx >> 6, c = idx & 63;
            sm[AJT_OFF + c * 65 + jl] = gAj[idx];
        }
        const float* gAi = g_Ai + (b * NPTS + it * 8) * 64;
        for (int idx = tid; idx < 512; idx += 256) {      // -> sAiT[k][il]
            int il = idx >> 6, c = idx & 63;
            sm[AIT_OFF + c * 8 + il] = gAi[idx];
        }
    }
    if (tid < 64)  sm[B2_OFF + tid] = b2[tid];
    if (tid < 128) sMax[tid] = 0u;
    __syncthreads();

    const int ii0 = tid >> 6;          // 0..3
    const int jj  = tid & 63;
    const int p0  = ii0 * 64 + jj;
    const int p1  = (ii0 + 4) * 64 + jj;

    // ---- layer 2: h2 = relu(W2 * relu(Ai+Aj) + b2), 2 pairs/thread, LDS.128 weights ----
    {
        unsigned long long acc0[32], acc1[32];
#pragma unroll
        for (int c2 = 0; c2 < 32; c2++) {
            unsigned long long bb = smu[B2_OFF / 2 + c2];
            acc0[c2] = bb; acc1[c2] = bb;
        }
#pragma unroll 2
        for (int k = 0; k < 64; k++) {
            float aj = sm[AJT_OFF + k * 65 + jj];
            float h0 = fmaxf(sm[AIT_OFF + k * 8 + ii0]     + aj, 0.f);
            float h1 = fmaxf(sm[AIT_OFF + k * 8 + ii0 + 4] + aj, 0.f);
            unsigned long long d0 = splat2(h0), d1 = splat2(h1);
            const ulonglong2* wrow = reinterpret_cast<const ulonglong2*>(sm + W2T_OFF + k * 68);
#pragma unroll
            for (int c4 = 0; c4 < 16; c4++) {
                ulonglong2 w = wrow[c4];                  // broadcast LDS.128: ch 4c4..4c4+3
                acc0[2 * c4]     = ffma2(d0, w.x, acc0[2 * c4]);
                acc0[2 * c4 + 1] = ffma2(d0, w.y, acc0[2 * c4 + 1]);
                acc1[2 * c4]     = ffma2(d1, w.x, acc1[2 * c4]);
                acc1[2 * c4 + 1] = ffma2(d1, w.y, acc1[2 * c4 + 1]);
            }
        }
        // relu + park h2 in SMEM [pair][ch], stride 68
#pragma unroll
        for (int c2 = 0; c2 < 32; c2++) {
            float lo, hi;
            unpack2(acc0[c2], lo, hi);
            smu[(H2_OFF + p0 * 68) / 2 + c2] = pack2(fmaxf(lo, 0.f), fmaxf(hi, 0.f));
            unpack2(acc1[c2], lo, hi);
            smu[(H2_OFF + p1 * 68) / 2 + c2] = pack2(fmaxf(lo, 0.f), fmaxf(hi, 0.f));
        }
    }
    __syncthreads();   // layer3 threads read other threads' h2

    // ---- layer 3: thread owns 8 pairs (all ii, fixed jj) x 32 ch (quarter g) ----
    const int g = tid >> 6;            // 0..3 -> channel quarter
#pragma unroll 1
    for (int chunk = 0; chunk < 2; chunk++) {
        const int cb = g * 32 + chunk * 16;   // 16 channels this pass
        unsigned long long acc[64];            // [m][cc] = m*8+cc
#pragma unroll
        for (int q = 0; q < 64; q++) acc[q] = 0ULL;

#pragma unroll 1
        for (int kb = 0; kb < 16; kb++) {
            float4 hv[8];
#pragma unroll
            for (int m = 0; m < 8; m++)        // LDS.128: h2[m*64+jj][4kb..+3]
                hv[m] = *reinterpret_cast<const float4*>(sm + H2_OFF + (m * 64 + jj) * 68 + kb * 4);
#pragma unroll
            for (int dk = 0; dk < 4; dk++) {
                const int k = kb * 4 + dk;
                const ulonglong2* wrow = reinterpret_cast<const ulonglong2*>(sm + W3T_OFF + k * 132 + cb);
                ulonglong2 wa = wrow[0], wb = wrow[1], wc = wrow[2], wd = wrow[3];
                unsigned long long w[8] = {wa.x, wa.y, wb.x, wb.y, wc.x, wc.y, wd.x, wd.y};
#pragma unroll
                for (int m = 0; m < 8; m++) {
                    float hm = (dk == 0) ? hv[m].x : (dk == 1) ? hv[m].y : (dk == 2) ? hv[m].z : hv[m].w;
                    unsigned long long d = splat2(hm);
#pragma unroll
                    for (int cc = 0; cc < 8; cc++)
                        acc[m * 8 + cc] = ffma2(d, w[cc], acc[m * 8 + cc]);
                }
            }
        }
        // max over this thread's 8 pairs
        unsigned long long mm[8];
#pragma unroll
        for (int cc = 0; cc < 8; cc++) {
            unsigned long long v = acc[cc];
#pragma unroll
            for (int m = 1; m < 8; m++) v = max2(v, acc[m * 8 + cc]);
            mm[cc] = v;
        }
        // reduce across the 32 lanes of the warp (32 distinct jj, same g)
#pragma unroll
        for (int off = 16; off > 0; off >>= 1) {
#pragma unroll
            for (int cc = 0; cc < 8; cc++) {
                unsigned long long o = __shfl_xor_sync(0xffffffffu, mm[cc], off);
                mm[cc] = max2(mm[cc], o);
            }
        }
        if ((tid & 31) == 0) {
#pragma unroll
            for (int cc = 0; cc < 8; cc++) {
                float lo, hi; unpack2(mm[cc], lo, hi);
                atomicMax(&sMax[cb + 2 * cc],     fkey(lo));
                atomicMax(&sMax[cb + 2 * cc + 1], fkey(hi));
            }
        }
    }
    __syncthreads();
    if (tid < 128) atomicMax(&g_Pkey[b * C3 + tid], sMax[tid]);
}

// ---------------- head MLP: one block per batch ----------------
__global__ void k_final(const float* __restrict__ b3, const float* __restrict__ F1,
                        const float* __restrict__ bf1, const float* __restrict__ F2,
                        const float* __restrict__ bf2, float* __restrict__ out) {
    __shared__ float sp[128];
    __shared__ float st[64];
    const int b = blockIdx.x;
    const int t = threadIdx.x;
    if (t < 128) sp[t] = funkey(g_Pkey[b * 128 + t]) + b3[t];
    __syncthreads();
    {
        const int r = t >> 2, q = t & 3;       // 4 threads per row
        float a = 0.f;
        const float* fr = F1 + r * 128 + q * 32;
#pragma unroll 8
        for (int c = 0; c < 32; c++) a += fr[c] * sp[q * 32 + c];
        a += __shfl_xor_sync(0xffffffffu, a, 1);
        a += __shfl_xor_sync(0xffffffffu, a, 2);
        if (q == 0) st[r] = fmaxf(a + bf1[r], 0.f);
    }
    __syncthreads();
    if (t < 2) {
        float a = bf2[t];
#pragma unroll
        for (int j = 0; j < 64; j++) a += F2[t * 64 + j] * st[j];
        out[b * 2 + t] = a;
    }
}

// ---------------- launch ----------------
extern "C" void kernel_launch(void* const* d_in, const int* in_sizes, int n_in,
                              void* d_out, int out_size) {
    const float* X   = (const float*)d_in[0];
    const float* W1  = (const float*)d_in[1];
    const float* b1  = (const float*)d_in[2];
    const float* W2  = (const float*)d_in[3];
    const float* b2  = (const float*)d_in[4];
    const float* W3  = (const float*)d_in[5];
    const float* b3  = (const float*)d_in[6];
    const float* F1  = (const float*)d_in[7];
    const float* bf1 = (const float*)d_in[8];
    const float* F2  = (const float*)d_in[9];
    const float* bf2 = (const float*)d_in[10];
    float* out = (float*)d_out;

    cudaFuncSetAttribute(k_main, cudaFuncAttributeMaxDynamicSharedMemorySize, SMEM_BYTES);

    k_pre<<<BATCH * NPTS, 64>>>(X, W1, b1);
    k_main<<<dim3(8, 64, BATCH), 256, SMEM_BYTES>>>(W2, b2, W3);
    k_final<<<BATCH, 256>>>(b3, F1, bf1, F2, bf2, out);
}

// round 6
// speedup vs baseline: 2.5572x; 2.0904x over previous
#include <cuda_runtime.h>
#include <cstdint>

// PointPairNet: B=4, N=512, D=3. pair-relu(64) -> 64 -> 128, global max-pool, head MLP.
// R4: mma.sync.m16n8k16 bf16 split (hi/lo 3-pass) on the HMMA pipe (plain sm_100 target).
// Tile = 128 pairs (2 i x 64 j). GEMM1 C-frags feed GEMM2 A-frags directly in registers.

#define BATCH 4
#define NPTS  512

__device__ float    g_Ai[BATCH * NPTS * 64];   // b1 folded in
__device__ float    g_Aj[BATCH * NPTS * 64];
__device__ unsigned g_Pkey[BATCH * 128];

// ---------------- helpers ----------------
static __device__ __forceinline__ unsigned fkey(float f) {
    unsigned u = __float_as_uint(f);
    return (u >> 31) ? ~u : (u | 0x80000000u);
}
static __device__ __forceinline__ float funkey(unsigned k) {
    return __uint_as_float((k >> 31) ? (k & 0x7fffffffu) : ~k);
}
static __device__ __forceinline__ uint32_t smem_u32(const void* p) {
    uint32_t a;
    asm("{ .reg .u64 t; cvta.to.shared.u64 t, %1; cvt.u32.u64 %0, t; }" : "=r"(a) : "l"(p));
    return a;
}
// split (f0,f1) fp32 -> bf16x2 hi (lo16=f0, hi16=f1) + bf16x2 residual lo
static __device__ __forceinline__ void split2(float f0, float f1, uint32_t& hi, uint32_t& lo) {
    asm("cvt.rn.bf16x2.f32 %0, %1, %2;" : "=r"(hi) : "f"(f1), "f"(f0));
    float h0 = __uint_as_float(hi << 16);
    float h1 = __uint_as_float(hi & 0xffff0000u);
    float l0 = f0 - h0, l1 = f1 - h1;
    asm("cvt.rn.bf16x2.f32 %0, %1, %2;" : "=r"(lo) : "f"(l1), "f"(l0));
}

#define LDSM_X4(r0, r1, r2, r3, a)                                                  \
    asm volatile("ldmatrix.sync.aligned.m8n8.x4.shared.b16 {%0,%1,%2,%3}, [%4];"    \
                 : "=r"(r0), "=r"(r1), "=r"(r2), "=r"(r3) : "r"(a))
#define LDSM_X4T(r0, r1, r2, r3, a)                                                 \
    asm volatile("ldmatrix.sync.aligned.m8n8.x4.trans.shared.b16 {%0,%1,%2,%3}, [%4];" \
                 : "=r"(r0), "=r"(r1), "=r"(r2), "=r"(r3) : "r"(a))

static __device__ __forceinline__ void mma_bf16(float* c, const uint32_t* a,
                                                uint32_t b0, uint32_t b1) {
    asm volatile("mma.sync.aligned.m16n8k16.row.col.f32.bf16.bf16.f32 "
                 "{%0,%1,%2,%3}, {%4,%5,%6,%7}, {%8,%9}, {%0,%1,%2,%3};"
                 : "+f"(c[0]), "+f"(c[1]), "+f"(c[2]), "+f"(c[3])
                 : "r"(a[0]), "r"(a[1]), "r"(a[2]), "r"(a[3]), "r"(b0), "r"(b1));
}

// ---------------- k_pre: layer-1 split + Pkey reset ----------------
__global__ void k_pre(const float* __restrict__ X, const float* __restrict__ W1,
                      const float* __restrict__ b1) {
    int ng = blockIdx.x;        // b*512+n
    int c  = threadIdx.x;       // 0..63
    if (ng < 8) g_Pkey[ng * 64 + c] = 0u;
    float x0 = X[ng * 3 + 0], x1 = X[ng * 3 + 1], x2 = X[ng * 3 + 2];
    const float* w = W1 + c * 6;
    g_Aj[ng * 64 + c] = x0 * w[0] + x1 * w[1] + x2 * w[2];
    g_Ai[ng * 64 + c] = b1[c] + x0 * w[3] + x1 * w[4] + x2 * w[5];
}

// ---------------- SMEM layout (bytes) ----------------
// Padded row strides (144 / 272 B) keep ldmatrix 8-row accesses conflict-free.
#define SM_B2   0          // 64 floats (256B)
#define SM_W2H  256        // [k=64][n=64] bf16, stride 144 -> 9216
#define SM_W2L  9472
#define SM_W3H  18688      // [k=64][n=128] bf16, stride 272 -> 17408
#define SM_W3L  36096
#define SM_H1H  53504      // [row=128][k=64] bf16, stride 144 -> 18432
#define SM_H1L  71936
#define SMEM_BYTES 90368

// ---------------- k_tensor: persistent, 256 threads, 8 warps ----------------
__global__ void __launch_bounds__(256, 1)
k_tensor(const float* __restrict__ W2, const float* __restrict__ b2,
         const float* __restrict__ W3) {
    extern __shared__ char smem[];
    const uint32_t smb = smem_u32(smem);
    float* smf = reinterpret_cast<float*>(smem);
    const int tid  = threadIdx.x;
    const int wid  = tid >> 5;
    const int lane = tid & 31;
    const int tig  = lane & 3;

    // ---- stage + split weights once (Wt[k][n] bf16 hi/lo, n-pairs packed) ----
    for (int i2 = tid; i2 < 2048; i2 += 256) {           // W2: 64n x 64k
        int k = i2 >> 5, np = i2 & 31;
        float w0 = W2[(2 * np) * 64 + k], w1 = W2[(2 * np + 1) * 64 + k];
        uint32_t hi, lo; split2(w0, w1, hi, lo);
        *reinterpret_cast<uint32_t*>(smem + SM_W2H + k * 144 + np * 4) = hi;
        *reinterpret_cast<uint32_t*>(smem + SM_W2L + k * 144 + np * 4) = lo;
    }
    for (int i2 = tid; i2 < 4096; i2 += 256) {           // W3: 128n x 64k
        int k = i2 >> 6, np = i2 & 63;
        float w0 = W3[(2 * np) * 64 + k], w1 = W3[(2 * np + 1) * 64 + k];
        uint32_t hi, lo; split2(w0, w1, hi, lo);
        *reinterpret_cast<uint32_t*>(smem + SM_W3H + k * 272 + np * 4) = hi;
        *reinterpret_cast<uint32_t*>(smem + SM_W3L + k * 272 + np * 4) = lo;
    }
    if (tid < 64) smf[SM_B2 / 4 + tid] = b2[tid];
    __syncthreads();

    // bias registers: bc[2nt], bc[2nt+1] = b2 at cols nt*8+2tig, +1
    float bc[16];
#pragma unroll
    for (int nt = 0; nt < 8; nt++) {
        bc[2 * nt]     = smf[SM_B2 / 4 + nt * 8 + 2 * tig];
        bc[2 * nt + 1] = smf[SM_B2 / 4 + nt * 8 + 2 * tig + 1];
    }

    // per-lane ldmatrix base addresses
    const int rowA = (wid << 4) + (lane & 7) + ((lane >> 3) & 1) * 8;
    const uint32_t aA  = smb + SM_H1H + rowA * 144 + ((lane >> 4) << 4);
    const int krow = (lane & 7) + ((lane >> 3) & 1) * 8;
    const uint32_t aW2 = smb + SM_W2H + krow * 144 + ((lane >> 4) << 4);
    const uint32_t aW3 = smb + SM_W3H + krow * 272 + ((lane >> 4) << 4);

    // H1 build indices: thread -> (row, k-half)
    const int brow = tid >> 1;              // 0..127
    const int bkh  = (tid & 1) * 32;        // k offset
    const int b_il = brow >> 6;             // i_local
    const int b_jl = brow & 63;             // j_local

    float maxv[32];
#pragma unroll
    for (int q = 0; q < 32; q++) maxv[q] = -3.4e38f;
    int cur_b = -1;

    for (int t = blockIdx.x; t < 8192; t += gridDim.x) {
        const int b = t >> 11, it = (t >> 3) & 255, jt = t & 7;
        if (b != cur_b) {
            if (cur_b >= 0) {
#pragma unroll
                for (int q = 0; q < 32; q++) {
                    float v = maxv[q];
                    v = fmaxf(v, __shfl_xor_sync(0xffffffffu, v, 4));
                    v = fmaxf(v, __shfl_xor_sync(0xffffffffu, v, 8));
                    v = fmaxf(v, __shfl_xor_sync(0xffffffffu, v, 16));
                    if (lane < 4)
                        atomicMax(&g_Pkey[cur_b * 128 + (q >> 1) * 8 + 2 * lane + (q & 1)], fkey(v));
                    maxv[q] = -3.4e38f;
                }
            }
            cur_b = b;
        }

        // ---- build H1 = relu(Ai + Aj) -> bf16 hi/lo SMEM ----
        {
            const float4* ajp = reinterpret_cast<const float4*>(
                g_Aj + ((b * NPTS + jt * 64 + b_jl) * 64 + bkh));
            const float4* aip = reinterpret_cast<const float4*>(
                g_Ai + ((b * NPTS + it * 2 + b_il) * 64 + bkh));
            uint32_t hh[16], ll[16];
#pragma unroll
            for (int u = 0; u < 8; u++) {
                float4 a = ajp[u], i = aip[u];
                float h0 = fmaxf(a.x + i.x, 0.f), h1 = fmaxf(a.y + i.y, 0.f);
                float h2 = fmaxf(a.z + i.z, 0.f), h3 = fmaxf(a.w + i.w, 0.f);
                split2(h0, h1, hh[2 * u], ll[2 * u]);
                split2(h2, h3, hh[2 * u + 1], ll[2 * u + 1]);
            }
            uint4* dh = reinterpret_cast<uint4*>(smem + SM_H1H + brow * 144 + bkh * 2);
            uint4* dl = reinterpret_cast<uint4*>(smem + SM_H1L + brow * 144 + bkh * 2);
#pragma unroll
            for (int u = 0; u < 4; u++) {
                dh[u] = make_uint4(hh[4 * u], hh[4 * u + 1], hh[4 * u + 2], hh[4 * u + 3]);
                dl[u] = make_uint4(ll[4 * u], ll[4 * u + 1], ll[4 * u + 2], ll[4 * u + 3]);
            }
        }
        __syncthreads();

        // ---- load A1 fragments (H1 hi/lo), then release H1 ----
        uint32_t a1h[16], a1l[16];
#pragma unroll
        for (int kt = 0; kt < 4; kt++) {
            LDSM_X4(a1h[4 * kt], a1h[4 * kt + 1], a1h[4 * kt + 2], a1h[4 * kt + 3], aA + kt * 32);
            LDSM_X4(a1l[4 * kt], a1l[4 * kt + 1], a1l[4 * kt + 2], a1l[4 * kt + 3],
                    aA + (SM_H1L - SM_H1H) + kt * 32);
        }
        __syncthreads();

        // ---- GEMM1: C1[16rows x 64ch] = H1 x W2^T (3-pass split) ----
        float c1[8][4];
#pragma unroll
        for (int nt = 0; nt < 8; nt++)
#pragma unroll
            for (int q = 0; q < 4; q++) c1[nt][q] = 0.f;
#pragma unroll
        for (int kt = 0; kt < 4; kt++) {
#pragma unroll
            for (int p = 0; p < 4; p++) {
                uint32_t bh0, bh1, bh2, bh3, bl0, bl1, bl2, bl3;
                LDSM_X4T(bh0, bh1, bh2, bh3, aW2 + kt * 2304 + p * 32);
                LDSM_X4T(bl0, bl1, bl2, bl3, aW2 + 9216 + kt * 2304 + p * 32);
                mma_bf16(c1[2 * p],     &a1h[4 * kt], bh0, bh1);
                mma_bf16(c1[2 * p],     &a1h[4 * kt], bl0, bl1);
                mma_bf16(c1[2 * p],     &a1l[4 * kt], bh0, bh1);
                mma_bf16(c1[2 * p + 1], &a1h[4 * kt], bh2, bh3);
                mma_bf16(c1[2 * p + 1], &a1h[4 * kt], bl2, bl3);
                mma_bf16(c1[2 * p + 1], &a1l[4 * kt], bh2, bh3);
            }
        }

        // ---- epilogue1: H2 = relu(C1 + b2); repack C-frags -> A2-frags ----
        uint32_t a2h[16], a2l[16];
#pragma unroll
        for (int kt2 = 0; kt2 < 4; kt2++) {
            const int na = 2 * kt2, nb = 2 * kt2 + 1;
            float e0 = fmaxf(c1[na][0] + bc[2 * na],     0.f);
            float e1 = fmaxf(c1[na][1] + bc[2 * na + 1], 0.f);
            float e2 = fmaxf(c1[na][2] + bc[2 * na],     0.f);
            float e3 = fmaxf(c1[na][3] + bc[2 * na + 1], 0.f);
            float f0 = fmaxf(c1[nb][0] + bc[2 * nb],     0.f);
            float f1 = fmaxf(c1[nb][1] + bc[2 * nb + 1], 0.f);
            float f2 = fmaxf(c1[nb][2] + bc[2 * nb],     0.f);
            float f3 = fmaxf(c1[nb][3] + bc[2 * nb + 1], 0.f);
            split2(e0, e1, a2h[4 * kt2 + 0], a2l[4 * kt2 + 0]);
            split2(e2, e3, a2h[4 * kt2 + 1], a2l[4 * kt2 + 1]);
            split2(f0, f1, a2h[4 * kt2 + 2], a2l[4 * kt2 + 2]);
            split2(f2, f3, a2h[4 * kt2 + 3], a2l[4 * kt2 + 3]);
        }

        // ---- GEMM2: D3[16rows x 128ch] = H2 x W3^T (3-pass split) ----
        float d3[16][4];
#pragma unroll
        for (int nt = 0; nt < 16; nt++)
#pragma unroll
            for (int q = 0; q < 4; q++) d3[nt][q] = 0.f;
#pragma unroll
        for (int kt2 = 0; kt2 < 4; kt2++) {
#pragma unroll
            for (int p = 0; p < 8; p++) {
                uint32_t bh0, bh1, bh2, bh3, bl0, bl1, bl2, bl3;
                LDSM_X4T(bh0, bh1, bh2, bh3, aW3 + kt2 * 4352 + p * 32);
                LDSM_X4T(bl0, bl1, bl2, bl3, aW3 + 17408 + kt2 * 4352 + p * 32);
                mma_bf16(d3[2 * p],     &a2h[4 * kt2], bh0, bh1);
                mma_bf16(d3[2 * p],     &a2h[4 * kt2], bl0, bl1);
                mma_bf16(d3[2 * p],     &a2l[4 * kt2], bh0, bh1);
                mma_bf16(d3[2 * p + 1], &a2h[4 * kt2], bh2, bh3);
                mma_bf16(d3[2 * p + 1], &a2h[4 * kt2], bl2, bl3);
                mma_bf16(d3[2 * p + 1], &a2l[4 * kt2], bh2, bh3);
            }
        }

        // ---- running max (b3 deferred to k_final) ----
#pragma unroll
        for (int nt = 0; nt < 16; nt++) {
            maxv[2 * nt]     = fmaxf(maxv[2 * nt],     fmaxf(d3[nt][0], d3[nt][2]));
            maxv[2 * nt + 1] = fmaxf(maxv[2 * nt + 1], fmaxf(d3[nt][1], d3[nt][3]));
        }
    }

    if (cur_b >= 0) {
#pragma unroll
        for (int q = 0; q < 32; q++) {
            float v = maxv[q];
            v = fmaxf(v, __shfl_xor_sync(0xffffffffu, v, 4));
            v = fmaxf(v, __shfl_xor_sync(0xffffffffu, v, 8));
            v = fmaxf(v, __shfl_xor_sync(0xffffffffu, v, 16));
            if (lane < 4)
                atomicMax(&g_Pkey[cur_b * 128 + (q >> 1) * 8 + 2 * lane + (q & 1)], fkey(v));
        }
    }
}

// ---------------- head MLP: one block per batch ----------------
__global__ void k_final(const float* __restrict__ b3, const float* __restrict__ F1,
                        const float* __restrict__ bf1, const float* __restrict__ F2,
                        const float* __restrict__ bf2, float* __restrict__ out) {
    __shared__ float sp[128];
    __shared__ float st[64];
    const int b = blockIdx.x;
    const int t = threadIdx.x;
    if (t < 128) sp[t] = funkey(g_Pkey[b * 128 + t]) + b3[t];
    __syncthreads();
    {
        const int r = t >> 2, q = t & 3;
        float a = 0.f;
        const float* fr = F1 + r * 128 + q * 32;
#pragma unroll 8
        for (int c = 0; c < 32; c++) a += fr[c] * sp[q * 32 + c];
        a += __shfl_xor_sync(0xffffffffu, a, 1);
        a += __shfl_xor_sync(0xffffffffu, a, 2);
        if (q == 0) st[r] = fmaxf(a + bf1[r], 0.f);
    }
    __syncthreads();
    if (t < 2) {
        float a = bf2[t];
#pragma unroll
        for (int j = 0; j < 64; j++) a += F2[t * 64 + j] * st[j];
        out[b * 2 + t] = a;
    }
}

// ---------------- launch ----------------
extern "C" void kernel_launch(void* const* d_in, const int* in_sizes, int n_in,
                              void* d_out, int out_size) {
    const float* X   = (const float*)d_in[0];
    const float* W1  = (const float*)d_in[1];
    const float* b1  = (const float*)d_in[2];
    const float* W2  = (const float*)d_in[3];
    const float* b2  = (const float*)d_in[4];
    const float* W3  = (const float*)d_in[5];
    const float* b3  = (const float*)d_in[6];
    const float* F1  = (const float*)d_in[7];
    const float* bf1 = (const float*)d_in[8];
    const float* F2  = (const float*)d_in[9];
    const float* bf2 = (const float*)d_in[10];
    float* out = (float*)d_out;

    cudaFuncSetAttribute(k_tensor, cudaFuncAttributeMaxDynamicSharedMemorySize, SMEM_BYTES);

    k_pre<<<BATCH * NPTS, 64>>>(X, W1, b1);
    k_tensor<<<148, 256, SMEM_BYTES>>>(W2, b2, W3);
    k_final<<<BATCH, 256>>>(b3, F1, bf1, F2, bf2, out);
}

// round 8
// speedup vs baseline: 3.0840x; 1.2060x over previous
#include <cuda_runtime.h>
#include <cuda_fp16.h>
#include <cstdint>

// PointPairNet: B=4, N=512, D=3. pair-relu(64) -> 64 -> 128, global max-pool, head MLP.
// R6: fp16 2-pass split MMA (A = hi+lo fp16, B = single fp16). m16n8k16 on HMMA pipe.
// Tile = 128 pairs (2 i x 64 j). GEMM1 C-frags feed GEMM2 A-frags directly in registers.

#define BATCH 4
#define NPTS  512

__device__ float    g_Ai[BATCH * NPTS * 64];   // b1 folded in
__device__ float    g_Aj[BATCH * NPTS * 64];
__device__ unsigned g_Pkey[BATCH * 128];

// ---------------- helpers ----------------
static __device__ __forceinline__ unsigned fkey(float f) {
    unsigned u = __float_as_uint(f);
    return (u >> 31) ? ~u : (u | 0x80000000u);
}
static __device__ __forceinline__ float funkey(unsigned k) {
    return __uint_as_float((k >> 31) ? (k & 0x7fffffffu) : ~k);
}
static __device__ __forceinline__ uint32_t smem_u32(const void* p) {
    uint32_t a;
    asm("{ .reg .u64 t; cvta.to.shared.u64 t, %1; cvt.u32.u64 %0, t; }" : "=r"(a) : "l"(p));
    return a;
}
// split (f0,f1) fp32 -> fp16x2 hi (lo16=f0, hi16=f1) + fp16x2 residual lo
static __device__ __forceinline__ void split2h(float f0, float f1, uint32_t& hi, uint32_t& lo) {
    __half2 h = __floats2half2_rn(f0, f1);
    hi = *reinterpret_cast<uint32_t*>(&h);
    float2 hf = __half22float2(h);
    __half2 l = __floats2half2_rn(f0 - hf.x, f1 - hf.y);
    lo = *reinterpret_cast<uint32_t*>(&l);
}
static __device__ __forceinline__ uint32_t cvt2h(float f0, float f1) {
    __half2 h = __floats2half2_rn(f0, f1);
    return *reinterpret_cast<uint32_t*>(&h);
}

#define LDSM_X4(r0, r1, r2, r3, a)                                                  \
    asm volatile("ldmatrix.sync.aligned.m8n8.x4.shared.b16 {%0,%1,%2,%3}, [%4];"    \
                 : "=r"(r0), "=r"(r1), "=r"(r2), "=r"(r3) : "r"(a))
#define LDSM_X4T(r0, r1, r2, r3, a)                                                 \
    asm volatile("ldmatrix.sync.aligned.m8n8.x4.trans.shared.b16 {%0,%1,%2,%3}, [%4];" \
                 : "=r"(r0), "=r"(r1), "=r"(r2), "=r"(r3) : "r"(a))

static __device__ __forceinline__ void mma_f16(float* c, const uint32_t* a,
                                               uint32_t b0, uint32_t b1) {
    asm volatile("mma.sync.aligned.m16n8k16.row.col.f32.f16.f16.f32 "
                 "{%0,%1,%2,%3}, {%4,%5,%6,%7}, {%8,%9}, {%0,%1,%2,%3};"
                 : "+f"(c[0]), "+f"(c[1]), "+f"(c[2]), "+f"(c[3])
                 : "r"(a[0]), "r"(a[1]), "r"(a[2]), "r"(a[3]), "r"(b0), "r"(b1));
}

// ---------------- k_pre: layer-1 split + Pkey reset ----------------
__global__ void k_pre(const float* __restrict__ X, const float* __restrict__ W1,
                      const float* __restrict__ b1) {
    int ng = blockIdx.x;        // b*512+n
    int c  = threadIdx.x;       // 0..63
    if (ng < 8) g_Pkey[ng * 64 + c] = 0u;
    float x0 = X[ng * 3 + 0], x1 = X[ng * 3 + 1], x2 = X[ng * 3 + 2];
    const float* w = W1 + c * 6;
    g_Aj[ng * 64 + c] = x0 * w[0] + x1 * w[1] + x2 * w[2];
    g_Ai[ng * 64 + c] = b1[c] + x0 * w[3] + x1 * w[4] + x2 * w[5];
}

// ---------------- SMEM layout (bytes) ----------------
// Padded row strides (144 / 272 B) keep ldmatrix 8-row accesses conflict-free.
#define SM_B2   0          // 64 floats (256B)
#define SM_W2   256        // [k=64][n=64] fp16, stride 144 -> 9216
#define SM_W3   9472       // [k=64][n=128] fp16, stride 272 -> 17408
#define SM_H1H  26880      // [row=128][k=64] fp16, stride 144 -> 18432
#define SM_H1L  45312
#define SMEM_BYTES 63744

// ---------------- k_tensor: persistent, 256 threads, 8 warps ----------------
__global__ void __launch_bounds__(256, 1)
k_tensor(const float* __restrict__ W2, const float* __restrict__ b2,
         const float* __restrict__ W3) {
    extern __shared__ char smem[];
    const uint32_t smb = smem_u32(smem);
    float* smf = reinterpret_cast<float*>(smem);
    const int tid  = threadIdx.x;
    const int wid  = tid >> 5;
    const int lane = tid & 31;
    const int tig  = lane & 3;

    // ---- stage weights once (Wt[k][n] fp16, n-pairs packed) ----
    for (int i2 = tid; i2 < 2048; i2 += 256) {           // W2: 64n x 64k
        int k = i2 >> 5, np = i2 & 31;
        *reinterpret_cast<uint32_t*>(smem + SM_W2 + k * 144 + np * 4) =
            cvt2h(W2[(2 * np) * 64 + k], W2[(2 * np + 1) * 64 + k]);
    }
    for (int i2 = tid; i2 < 4096; i2 += 256) {           // W3: 128n x 64k
        int k = i2 >> 6, np = i2 & 63;
        *reinterpret_cast<uint32_t*>(smem + SM_W3 + k * 272 + np * 4) =
            cvt2h(W3[(2 * np) * 64 + k], W3[(2 * np + 1) * 64 + k]);
    }
    if (tid < 64) smf[SM_B2 / 4 + tid] = b2[tid];
    __syncthreads();

    // bias registers: bc[2nt], bc[2nt+1] = b2 at cols nt*8+2tig, +1
    float bc[16];
#pragma unroll
    for (int nt = 0; nt < 8; nt++) {
        bc[2 * nt]     = smf[SM_B2 / 4 + nt * 8 + 2 * tig];
        bc[2 * nt + 1] = smf[SM_B2 / 4 + nt * 8 + 2 * tig + 1];
    }

    // per-lane ldmatrix base addresses
    const int rowA = (wid << 4) + (lane & 7) + ((lane >> 3) & 1) * 8;
    const uint32_t aA  = smb + SM_H1H + rowA * 144 + ((lane >> 4) << 4);
    const int krow = (lane & 7) + ((lane >> 3) & 1) * 8;
    const uint32_t aW2 = smb + SM_W2 + krow * 144 + ((lane >> 4) << 4);
    const uint32_t aW3 = smb + SM_W3 + krow * 272 + ((lane >> 4) << 4);

    // H1 build indices: thread -> (row, k-half)
    const int brow = tid >> 1;              // 0..127
    const int bkh  = (tid & 1) * 32;        // k offset
    const int b_il = brow >> 6;             // i_local
    const int b_jl = brow & 63;             // j_local

    float maxv[32];
#pragma unroll
    for (int q = 0; q < 32; q++) maxv[q] = -3.4e38f;
    int cur_b = -1;

    for (int t = blockIdx.x; t < 8192; t += gridDim.x) {
        const int b = t >> 11, it = (t >> 3) & 255, jt = t & 7;
        if (b != cur_b) {
            if (cur_b >= 0) {
#pragma unroll
                for (int q = 0; q < 32; q++) {
                    float v = maxv[q];
                    v = fmaxf(v, __shfl_xor_sync(0xffffffffu, v, 4));
                    v = fmaxf(v, __shfl_xor_sync(0xffffffffu, v, 8));
                    v = fmaxf(v, __shfl_xor_sync(0xffffffffu, v, 16));
                    if (lane < 4)
                        atomicMax(&g_Pkey[cur_b * 128 + (q >> 1) * 8 + 2 * lane + (q & 1)], fkey(v));
                    maxv[q] = -3.4e38f;
                }
            }
            cur_b = b;
        }

        // ---- build H1 = relu(Ai + Aj) -> fp16 hi/lo SMEM ----
        {
            const float4* ajp = reinterpret_cast<const float4*>(
                g_Aj + ((b * NPTS + jt * 64 + b_jl) * 64 + bkh));
            const float4* aip = reinterpret_cast<const float4*>(
                g_Ai + ((b * NPTS + it * 2 + b_il) * 64 + bkh));
            uint32_t hh[16], ll[16];
#pragma unroll
            for (int u = 0; u < 8; u++) {
                float4 a = ajp[u], i = aip[u];
                float h0 = fmaxf(a.x + i.x, 0.f), h1 = fmaxf(a.y + i.y, 0.f);
                float h2 = fmaxf(a.z + i.z, 0.f), h3 = fmaxf(a.w + i.w, 0.f);
                split2h(h0, h1, hh[2 * u], ll[2 * u]);
                split2h(h2, h3, hh[2 * u + 1], ll[2 * u + 1]);
            }
            uint4* dh = reinterpret_cast<uint4*>(smem + SM_H1H + brow * 144 + bkh * 2);
            uint4* dl = reinterpret_cast<uint4*>(smem + SM_H1L + brow * 144 + bkh * 2);
#pragma unroll
            for (int u = 0; u < 4; u++) {
                dh[u] = make_uint4(hh[4 * u], hh[4 * u + 1], hh[4 * u + 2], hh[4 * u + 3]);
                dl[u] = make_uint4(ll[4 * u], ll[4 * u + 1], ll[4 * u + 2], ll[4 * u + 3]);
            }
        }
        __syncthreads();

        // ---- load A1 fragments (H1 hi/lo), then release H1 ----
        uint32_t a1h[16], a1l[16];
#pragma unroll
        for (int kt = 0; kt < 4; kt++) {
            LDSM_X4(a1h[4 * kt], a1h[4 * kt + 1], a1h[4 * kt + 2], a1h[4 * kt + 3], aA + kt * 32);
            LDSM_X4(a1l[4 * kt], a1l[4 * kt + 1], a1l[4 * kt + 2], a1l[4 * kt + 3],
                    aA + (SM_H1L - SM_H1H) + kt * 32);
        }
        __syncthreads();

        // ---- GEMM1: C1[16rows x 64ch] = H1 x W2^T (2-pass: (ah+al) x bh) ----
        float c1[8][4];
#pragma unroll
        for (int nt = 0; nt < 8; nt++)
#pragma unroll
            for (int q = 0; q < 4; q++) c1[nt][q] = 0.f;
#pragma unroll
        for (int kt = 0; kt < 4; kt++) {
#pragma unroll
            for (int p = 0; p < 4; p++) {
                uint32_t bh0, bh1, bh2, bh3;
                LDSM_X4T(bh0, bh1, bh2, bh3, aW2 + kt * 2304 + p * 32);
                mma_f16(c1[2 * p],     &a1h[4 * kt], bh0, bh1);
                mma_f16(c1[2 * p],     &a1l[4 * kt], bh0, bh1);
                mma_f16(c1[2 * p + 1], &a1h[4 * kt], bh2, bh3);
                mma_f16(c1[2 * p + 1], &a1l[4 * kt], bh2, bh3);
            }
        }

        // ---- epilogue1: H2 = relu(C1 + b2); repack C-frags -> A2-frags ----
        uint32_t a2h[16], a2l[16];
#pragma unroll
        for (int kt2 = 0; kt2 < 4; kt2++) {
            const int na = 2 * kt2, nb = 2 * kt2 + 1;
            float e0 = fmaxf(c1[na][0] + bc[2 * na],     0.f);
            float e1 = fmaxf(c1[na][1] + bc[2 * na + 1], 0.f);
            float e2 = fmaxf(c1[na][2] + bc[2 * na],     0.f);
            float e3 = fmaxf(c1[na][3] + bc[2 * na + 1], 0.f);
            float f0 = fmaxf(c1[nb][0] + bc[2 * nb],     0.f);
            float f1 = fmaxf(c1[nb][1] + bc[2 * nb + 1], 0.f);
            float f2 = fmaxf(c1[nb][2] + bc[2 * nb],     0.f);
            float f3 = fmaxf(c1[nb][3] + bc[2 * nb + 1], 0.f);
            split2h(e0, e1, a2h[4 * kt2 + 0], a2l[4 * kt2 + 0]);
            split2h(e2, e3, a2h[4 * kt2 + 1], a2l[4 * kt2 + 1]);
            split2h(f0, f1, a2h[4 * kt2 + 2], a2l[4 * kt2 + 2]);
            split2h(f2, f3, a2h[4 * kt2 + 3], a2l[4 * kt2 + 3]);
        }

        // ---- GEMM2: D3[16rows x 128ch] = H2 x W3^T (2-pass) ----
        float d3[16][4];
#pragma unroll
        for (int nt = 0; nt < 16; nt++)
#pragma unroll
            for (int q = 0; q < 4; q++) d3[nt][q] = 0.f;
#pragma unroll
        for (int kt2 = 0; kt2 < 4; kt2++) {
#pragma unroll
            for (int p = 0; p < 8; p++) {
                uint32_t bh0, bh1, bh2, bh3;
                LDSM_X4T(bh0, bh1, bh2, bh3, aW3 + kt2 * 4352 + p * 32);
                mma_f16(d3[2 * p],     &a2h[4 * kt2], bh0, bh1);
                mma_f16(d3[2 * p],     &a2l[4 * kt2], bh0, bh1);
                mma_f16(d3[2 * p + 1], &a2h[4 * kt2], bh2, bh3);
                mma_f16(d3[2 * p + 1], &a2l[4 * kt2], bh2, bh3);
            }
        }

        // ---- running max (b3 deferred to k_final) ----
#pragma unroll
        for (int nt = 0; nt < 16; nt++) {
            maxv[2 * nt]     = fmaxf(maxv[2 * nt],     fmaxf(d3[nt][0], d3[nt][2]));
            maxv[2 * nt + 1] = fmaxf(maxv[2 * nt + 1], fmaxf(d3[nt][1], d3[nt][3]));
        }
    }

    if (cur_b >= 0) {
#pragma unroll
        for (int q = 0; q < 32; q++) {
            float v = maxv[q];
            v = fmaxf(v, __shfl_xor_sync(0xffffffffu, v, 4));
            v = fmaxf(v, __shfl_xor_sync(0xffffffffu, v, 8));
            v = fmaxf(v, __shfl_xor_sync(0xffffffffu, v, 16));
            if (lane < 4)
                atomicMax(&g_Pkey[cur_b * 128 + (q >> 1) * 8 + 2 * lane + (q & 1)], fkey(v));
        }
    }
}

// ---------------- head MLP: one block per batch ----------------
__global__ void k_final(const float* __restrict__ b3, const float* __restrict__ F1,
                        const float* __restrict__ bf1, const float* __restrict__ F2,
                        const float* __restrict__ bf2, float* __restrict__ out) {
    __shared__ float sp[128];
    __shared__ float st[64];
    const int b = blockIdx.x;
    const int t = threadIdx.x;
    if (t < 128) sp[t] = funkey(g_Pkey[b * 128 + t]) + b3[t];
    __syncthreads();
    {
        const int r = t >> 2, q = t & 3;
        float a = 0.f;
        const float* fr = F1 + r * 128 + q * 32;
#pragma unroll 8
        for (int c = 0; c < 32; c++) a += fr[c] * sp[q * 32 + c];
        a += __shfl_xor_sync(0xffffffffu, a, 1);
        a += __shfl_xor_sync(0xffffffffu, a, 2);
        if (q == 0) st[r] = fmaxf(a + bf1[r], 0.f);
    }
    __syncthreads();
    if (t < 2) {
        float a = bf2[t];
#pragma unroll
        for (int j = 0; j < 64; j++) a += F2[t * 64 + j] * st[j];
        out[b * 2 + t] = a;
    }
}

// ---------------- launch ----------------
extern "C" void kernel_launch(void* const* d_in, const int* in_sizes, int n_in,
                              void* d_out, int out_size) {
    const float* X   = (const float*)d_in[0];
    const float* W1  = (const float*)d_in[1];
    const float* b1  = (const float*)d_in[2];
    const float* W2  = (const float*)d_in[3];
    const float* b2  = (const float*)d_in[4];
    const float* W3  = (const float*)d_in[5];
    const float* b3  = (const float*)d_in[6];
    const float* F1  = (const float*)d_in[7];
    const float* bf1 = (const float*)d_in[8];
    const float* F2  = (const float*)d_in[9];
    const float* bf2 = (const float*)d_in[10];
    float* out = (float*)d_out;

    cudaFuncSetAttribute(k_tensor, cudaFuncAttributeMaxDynamicSharedMemorySize, SMEM_BYTES);

    k_pre<<<BATCH * NPTS, 64>>>(X, W1, b1);
    k_tensor<<<148, 256, SMEM_BYTES>>>(W2, b2, W3);
    k_final<<<BATCH, 256>>>(b3, F1, bf1, F2, bf2, out);
}